// round 1
// baseline (speedup 1.0000x reference)
#include <cuda_runtime.h>
#include <cuda_bf16.h>

// FSRCNN: BS=1024, D=56, S=12, H=W=32 -> out 3x64x64
// Inputs (metadata order):
// 0 x[1024,3,32,32] 1 head_w[56,3,5,5] 2 head_b[56] 3 head_a[56]
// 4 b0_w[12,56,1,1] 5 b0_b[12] 6 b0_a[12]
// 7 b1_w[12,12,3,3] 8 b1_b 9 b2_w 10 b2_b 11 b3_w 12 b3_b 13 b4_w 14 b4_b
// 15 b5_a[12] 16 b6_w[56,12,1,1] 17 b6_b[56] 18 b6_a[56]
// 19 tail_w[56,3,9,9] 20 tail_b[3]

__device__ float g_h1[1024 * 12 * 1024];   // after b0 + prelu
__device__ float g_h5[1024 * 12 * 1024];   // after b4 + prelu(b5_a)
__device__ float g_h6[1024 * 56 * 1024];   // after b6 + prelu

// ---------------------------------------------------------------------------
// Kernel 1: head 5x5 conv (3->56, pad2) + PReLU + b0 1x1 (56->12) + PReLU
// One block per image, 256 threads, 4 pixels/thread. 56-ch tensor stays in regs.
// ---------------------------------------------------------------------------
__global__ __launch_bounds__(256) void k_head(
    const float* __restrict__ x,
    const float* __restrict__ head_w, const float* __restrict__ head_b,
    const float* __restrict__ head_a,
    const float* __restrict__ b0_w, const float* __restrict__ b0_b,
    const float* __restrict__ b0_a)
{
    __shared__ float xs[3 * 1024];
    __shared__ __align__(16) float wh[56 * 76];   // 75 taps padded to 76
    __shared__ float hb[56], ha[56];
    __shared__ __align__(16) float w0s[56 * 12];  // [oc56][s12]
    __shared__ float b0bs[12], b0as[12];

    const int tid = threadIdx.x;
    const int img = blockIdx.x;

    const float* xim = x + img * 3072;
    for (int i = tid; i < 3072; i += 256) xs[i] = xim[i];
    for (int i = tid; i < 56 * 76; i += 256) {
        int oc = i / 76, t = i % 76;
        wh[i] = (t < 75) ? head_w[oc * 75 + t] : 0.f;
    }
    if (tid < 56) { hb[tid] = head_b[tid]; ha[tid] = head_a[tid]; }
    for (int i = tid; i < 672; i += 256) {
        int oc = i / 12, s = i % 12;
        w0s[i] = b0_w[s * 56 + oc];
    }
    if (tid < 12) { b0bs[tid] = b0_b[tid]; b0as[tid] = b0_a[tid]; }
    __syncthreads();

    float* out = g_h1 + img * 12288;

    for (int k = 0; k < 4; k++) {
        const int pix = k * 256 + tid;
        const int y = pix >> 5, x0 = pix & 31;

        float xr[76];
        xr[75] = 0.f;
#pragma unroll
        for (int ic = 0; ic < 3; ic++)
#pragma unroll
        for (int ky = 0; ky < 5; ky++) {
            const int yy = y + ky - 2;
#pragma unroll
            for (int kx = 0; kx < 5; kx++) {
                const int xx = x0 + kx - 2;
                const bool ok = (yy >= 0) & (yy < 32) & (xx >= 0) & (xx < 32);
                xr[ic * 25 + ky * 5 + kx] = ok ? xs[ic * 1024 + yy * 32 + xx] : 0.f;
            }
        }

        float acc[12];
#pragma unroll
        for (int s = 0; s < 12; s++) acc[s] = b0bs[s];

#pragma unroll 1
        for (int oc = 0; oc < 56; oc++) {
            float a = hb[oc];
            const float4* wp = (const float4*)(wh + oc * 76);
#pragma unroll
            for (int j = 0; j < 19; j++) {
                float4 w4 = wp[j];
                a = fmaf(xr[4 * j + 0], w4.x, a);
                a = fmaf(xr[4 * j + 1], w4.y, a);
                a = fmaf(xr[4 * j + 2], w4.z, a);
                a = fmaf(xr[4 * j + 3], w4.w, a);
            }
            const float h = (a >= 0.f) ? a : ha[oc] * a;
            const float4* q = (const float4*)(w0s + oc * 12);
            float4 q0 = q[0], q1 = q[1], q2 = q[2];
            acc[0]  = fmaf(h, q0.x, acc[0]);  acc[1]  = fmaf(h, q0.y, acc[1]);
            acc[2]  = fmaf(h, q0.z, acc[2]);  acc[3]  = fmaf(h, q0.w, acc[3]);
            acc[4]  = fmaf(h, q1.x, acc[4]);  acc[5]  = fmaf(h, q1.y, acc[5]);
            acc[6]  = fmaf(h, q1.z, acc[6]);  acc[7]  = fmaf(h, q1.w, acc[7]);
            acc[8]  = fmaf(h, q2.x, acc[8]);  acc[9]  = fmaf(h, q2.y, acc[9]);
            acc[10] = fmaf(h, q2.z, acc[10]); acc[11] = fmaf(h, q2.w, acc[11]);
        }

#pragma unroll
        for (int s = 0; s < 12; s++) {
            float v = acc[s];
            v = (v >= 0.f) ? v : b0as[s] * v;
            out[s * 1024 + pix] = v;
        }
    }
}

// ---------------------------------------------------------------------------
// Kernel 2: four 3x3 convs (12->12, pad1), PReLU(b5_a) after the last.
// One block per image; both 12x32x32 maps live in smem (double buffer).
// ---------------------------------------------------------------------------
__global__ __launch_bounds__(256) void k_body(
    const float* __restrict__ w1, const float* __restrict__ bb1,
    const float* __restrict__ w2, const float* __restrict__ bb2,
    const float* __restrict__ w3, const float* __restrict__ bb3,
    const float* __restrict__ w4, const float* __restrict__ bb4,
    const float* __restrict__ b5a)
{
    extern __shared__ float sm[];
    float* buf0 = sm;              // 12288
    float* buf1 = sm + 12288;      // 12288
    float* ws   = sm + 24576;      // 4*1728 = 6912, [l][oc][ic][12pad]
    float* bs   = sm + 31488;      // 48
    float* a5   = sm + 31536;      // 12

    const int tid = threadIdx.x;
    const int img = blockIdx.x;

    const float* wl[4] = {w1, w2, w3, w4};
    const float* bl[4] = {bb1, bb2, bb3, bb4};
    for (int l = 0; l < 4; l++) {
        const float* w = wl[l];
        for (int i = tid; i < 1728; i += 256) {
            int pr = i / 12, t = i % 12;          // pr = oc*12+ic
            ws[l * 1728 + i] = (t < 9) ? w[pr * 9 + t] : 0.f;
        }
        if (tid < 12) bs[l * 12 + tid] = bl[l][tid];
    }
    if (tid < 12) a5[tid] = b5a[tid];

    const float* src_g = g_h1 + img * 12288;
    for (int i = tid; i < 12288; i += 256) buf0[i] = src_g[i];
    __syncthreads();

    float* gout = g_h5 + img * 12288;
    float* bufs[2] = {buf0, buf1};

    for (int l = 0; l < 4; l++) {
        const float* src = bufs[l & 1];
        float* dst = bufs[(l & 1) ^ 1];
        const float* w = ws + l * 1728;
        const float* bb = bs + l * 12;

        for (int k = 0; k < 4; k++) {
            const int pix = k * 256 + tid;
            const int y = pix >> 5, x = pix & 31;
            float acc[12];
#pragma unroll
            for (int o = 0; o < 12; o++) acc[o] = bb[o];

            const bool yu = y > 0, yd = y < 31, xl = x > 0, xr = x < 31;
#pragma unroll 1
            for (int ic = 0; ic < 12; ic++) {
                const float* sp = src + ic * 1024 + y * 32 + x;
                const float n0 = (yu && xl) ? sp[-33] : 0.f;
                const float n1 = yu ? sp[-32] : 0.f;
                const float n2 = (yu && xr) ? sp[-31] : 0.f;
                const float n3 = xl ? sp[-1] : 0.f;
                const float n4 = sp[0];
                const float n5 = xr ? sp[1] : 0.f;
                const float n6 = (yd && xl) ? sp[31] : 0.f;
                const float n7 = yd ? sp[32] : 0.f;
                const float n8 = (yd && xr) ? sp[33] : 0.f;
#pragma unroll
                for (int oc = 0; oc < 12; oc++) {
                    const float4* wp = (const float4*)(w + (oc * 12 + ic) * 12);
                    float4 a0 = wp[0], a1 = wp[1], a2 = wp[2];
                    float s0 = acc[oc];
                    s0 = fmaf(n0, a0.x, s0); s0 = fmaf(n1, a0.y, s0);
                    s0 = fmaf(n2, a0.z, s0); s0 = fmaf(n3, a0.w, s0);
                    s0 = fmaf(n4, a1.x, s0); s0 = fmaf(n5, a1.y, s0);
                    s0 = fmaf(n6, a1.z, s0); s0 = fmaf(n7, a1.w, s0);
                    s0 = fmaf(n8, a2.x, s0);
                    acc[oc] = s0;
                }
            }

            if (l == 3) {
#pragma unroll
                for (int oc = 0; oc < 12; oc++) {
                    float v = acc[oc];
                    v = (v >= 0.f) ? v : a5[oc] * v;
                    gout[oc * 1024 + pix] = v;
                }
            } else {
#pragma unroll
                for (int oc = 0; oc < 12; oc++)
                    dst[oc * 1024 + pix] = acc[oc];
            }
        }
        __syncthreads();
    }
}

// ---------------------------------------------------------------------------
// Kernel 3: b6 1x1 (12->56) + PReLU. Thread per pixel.
// ---------------------------------------------------------------------------
__global__ __launch_bounds__(256) void k_expand(
    const float* __restrict__ b6_w, const float* __restrict__ b6_b,
    const float* __restrict__ b6_a)
{
    __shared__ __align__(16) float ws[672];   // [oc56][s12]
    __shared__ float bb[56], aa[56];

    const int tid = threadIdx.x;
    const int bid = blockIdx.x;
    const int img = bid >> 2;
    const int pix = ((bid & 3) << 8) + tid;

    for (int i = tid; i < 672; i += 256) ws[i] = b6_w[i];
    if (tid < 56) { bb[tid] = b6_b[tid]; aa[tid] = b6_a[tid]; }
    __syncthreads();

    const float* in = g_h5 + img * 12288 + pix;
    float v[12];
#pragma unroll
    for (int s = 0; s < 12; s++) v[s] = in[s * 1024];

    float* out = g_h6 + img * 57344 + pix;
#pragma unroll 1
    for (int oc = 0; oc < 56; oc++) {
        const float4* wp = (const float4*)(ws + oc * 12);
        float4 a0 = wp[0], a1 = wp[1], a2 = wp[2];
        float a = bb[oc];
        a = fmaf(v[0], a0.x, a); a = fmaf(v[1], a0.y, a);
        a = fmaf(v[2], a0.z, a); a = fmaf(v[3], a0.w, a);
        a = fmaf(v[4], a1.x, a); a = fmaf(v[5], a1.y, a);
        a = fmaf(v[6], a1.z, a); a = fmaf(v[7], a1.w, a);
        a = fmaf(v[8], a2.x, a); a = fmaf(v[9], a2.y, a);
        a = fmaf(v[10], a2.z, a); a = fmaf(v[11], a2.w, a);
        a = (a >= 0.f) ? a : aa[oc] * a;
        out[oc * 1024] = a;
    }
}

// ---------------------------------------------------------------------------
// Kernel 4: 9x9 stride-2 transposed conv (56->3), pad4, outpad1.
// out[oc][oy][ox] = b[oc] + sum_{c,ky,kx: oy=2*iy+ky-4, ox=2*ix+kx-4} h6[c][iy][ix]*w[c][oc][ky][kx]
// Block = one image quadrant of output (32x32). Parity decomposition: each
// warp-pair handles one (oy,ox) parity class -> warp-uniform tap loops.
// Input tile zero-padded in smem -> no bounds checks in hot loop.
// ---------------------------------------------------------------------------
__global__ __launch_bounds__(256) void k_tail(
    const float* __restrict__ tail_w, const float* __restrict__ tail_b,
    float* __restrict__ out)
{
    extern __shared__ float sm[];
    float* h6s = sm;            // 56*20*20 = 22400, [c][r20][s20]
    float* wt  = sm + 22400;    // 81*56*4 = 18144, [tap81][c56][oc4pad]
    float* tb  = sm + 40544;    // 4

    const int tid = threadIdx.x;
    const int bid = blockIdx.x;
    const int img = bid >> 2;
    const int tIdx = bid & 3;
    const int OY0 = (tIdx >> 1) * 32, OX0 = (tIdx & 1) * 32;
    const int IY0 = OY0 / 2 - 2, IX0 = OX0 / 2 - 2;

    for (int i = tid; i < 81 * 56 * 4; i += 256) {
        const int oc = i & 3;
        const int rest = i >> 2;
        const int c = rest % 56;
        const int t = rest / 56;             // ky*9+kx
        wt[i] = (oc < 3) ? tail_w[c * 243 + oc * 81 + t] : 0.f;
    }
    const float* h6g = g_h6 + img * 57344;
    for (int i = tid; i < 56 * 400; i += 256) {
        const int c = i / 400;
        const int r = (i % 400) / 20;
        const int s = i % 20;
        const int iy = IY0 + r, ix = IX0 + s;
        float v = 0.f;
        if (iy >= 0 && iy < 32 && ix >= 0 && ix < 32)
            v = h6g[c * 1024 + iy * 32 + ix];
        h6s[i] = v;
    }
    if (tid < 3) tb[tid] = tail_b[tid];
    __syncthreads();

    const int phase = tid >> 6;        // warp-pair per parity class
    const int ry = phase & 1, rx = phase >> 1;
    const int t64 = tid & 63;
    const int sx = t64 & 15, sy0 = t64 >> 4;   // 4 pixels: rows sy0+4p, col sx
    const int nky = 5 - ry, nkx = 5 - rx;

    float acc[4][3];
#pragma unroll
    for (int p = 0; p < 4; p++)
#pragma unroll
        for (int o = 0; o < 3; o++) acc[p][o] = tb[o];

#pragma unroll 1
    for (int a = 0; a < nky; a++) {
        const int ky = (ry == 0) ? (8 - 2 * a) : (7 - 2 * a);
        const int dr = (ry == 0) ? a : (a + 1);
#pragma unroll 1
        for (int b = 0; b < nkx; b++) {
            const int kx = (rx == 0) ? (8 - 2 * b) : (7 - 2 * b);
            const int dc = (rx == 0) ? b : (b + 1);
            const float* wp = wt + (ky * 9 + kx) * 56 * 4;
            const float* hp = h6s + (sy0 + dr) * 20 + (sx + dc);
#pragma unroll 4
            for (int c = 0; c < 56; c++) {
                const float4 w4 = *(const float4*)(wp + c * 4);   // broadcast
                const float h0 = hp[c * 400];
                const float h1 = hp[c * 400 + 80];
                const float h2 = hp[c * 400 + 160];
                const float h3 = hp[c * 400 + 240];
                acc[0][0] = fmaf(h0, w4.x, acc[0][0]);
                acc[0][1] = fmaf(h0, w4.y, acc[0][1]);
                acc[0][2] = fmaf(h0, w4.z, acc[0][2]);
                acc[1][0] = fmaf(h1, w4.x, acc[1][0]);
                acc[1][1] = fmaf(h1, w4.y, acc[1][1]);
                acc[1][2] = fmaf(h1, w4.z, acc[1][2]);
                acc[2][0] = fmaf(h2, w4.x, acc[2][0]);
                acc[2][1] = fmaf(h2, w4.y, acc[2][1]);
                acc[2][2] = fmaf(h2, w4.z, acc[2][2]);
                acc[3][0] = fmaf(h3, w4.x, acc[3][0]);
                acc[3][1] = fmaf(h3, w4.y, acc[3][1]);
                acc[3][2] = fmaf(h3, w4.z, acc[3][2]);
            }
        }
    }

    float* o = out + img * 3 * 4096;
#pragma unroll
    for (int p = 0; p < 4; p++) {
        const int oy = OY0 + 2 * (sy0 + 4 * p) + ry;
        const int ox = OX0 + 2 * sx + rx;
#pragma unroll
        for (int oc = 0; oc < 3; oc++)
            o[oc * 4096 + oy * 64 + ox] = acc[p][oc];
    }
}

// ---------------------------------------------------------------------------
extern "C" void kernel_launch(void* const* d_in, const int* in_sizes, int n_in,
                              void* d_out, int out_size)
{
    const float* x      = (const float*)d_in[0];
    const float* head_w = (const float*)d_in[1];
    const float* head_b = (const float*)d_in[2];
    const float* head_a = (const float*)d_in[3];
    const float* b0_w   = (const float*)d_in[4];
    const float* b0_b   = (const float*)d_in[5];
    const float* b0_a   = (const float*)d_in[6];
    const float* b1_w   = (const float*)d_in[7];
    const float* b1_b   = (const float*)d_in[8];
    const float* b2_w   = (const float*)d_in[9];
    const float* b2_b   = (const float*)d_in[10];
    const float* b3_w   = (const float*)d_in[11];
    const float* b3_b   = (const float*)d_in[12];
    const float* b4_w   = (const float*)d_in[13];
    const float* b4_b   = (const float*)d_in[14];
    const float* b5_a   = (const float*)d_in[15];
    const float* b6_w   = (const float*)d_in[16];
    const float* b6_b   = (const float*)d_in[17];
    const float* b6_a   = (const float*)d_in[18];
    const float* tail_w = (const float*)d_in[19];
    const float* tail_b = (const float*)d_in[20];

    const int SM2 = 31548 * 4;   // k_body dynamic smem
    const int SM4 = 40548 * 4;   // k_tail dynamic smem
    cudaFuncSetAttribute(k_body, cudaFuncAttributeMaxDynamicSharedMemorySize, SM2);
    cudaFuncSetAttribute(k_tail, cudaFuncAttributeMaxDynamicSharedMemorySize, SM4);

    k_head<<<1024, 256>>>(x, head_w, head_b, head_a, b0_w, b0_b, b0_a);
    k_body<<<1024, 256, SM2>>>(b1_w, b1_b, b2_w, b2_b, b3_w, b3_b, b4_w, b4_b, b5_a);
    k_expand<<<4096, 256>>>(b6_w, b6_b, b6_a);
    k_tail<<<4096, 256, SM4>>>(tail_w, tail_b, (float*)d_out);
}

// round 2
// speedup vs baseline: 1.3187x; 1.3187x over previous
#include <cuda_runtime.h>
#include <cuda_bf16.h>

// FSRCNN: BS=1024, D=56, S=12, H=W=32 -> out 3x64x64
// 0 x[1024,3,32,32] 1 head_w[56,3,5,5] 2 head_b[56] 3 head_a[56]
// 4 b0_w[12,56,1,1] 5 b0_b[12] 6 b0_a[12]
// 7 b1_w[12,12,3,3] 8 b1_b 9 b2_w 10 b2_b 11 b3_w 12 b3_b 13 b4_w 14 b4_b
// 15 b5_a[12] 16 b6_w[56,12,1,1] 17 b6_b[56] 18 b6_a[56]
// 19 tail_w[56,3,9,9] 20 tail_b[3]

__device__ float g_h1[1024 * 12 * 1024];   // after b0 + prelu
__device__ float g_h5[1024 * 12 * 1024];   // after b4 + prelu(b5_a)

// ---------------------------------------------------------------------------
// Kernel 1: head 5x5 conv (3->56, pad2) + PReLU + b0 1x1 (56->12) + PReLU
// ---------------------------------------------------------------------------
__global__ __launch_bounds__(256) void k_head(
    const float* __restrict__ x,
    const float* __restrict__ head_w, const float* __restrict__ head_b,
    const float* __restrict__ head_a,
    const float* __restrict__ b0_w, const float* __restrict__ b0_b,
    const float* __restrict__ b0_a)
{
    __shared__ float xs[3 * 1024];
    __shared__ __align__(16) float wh[56 * 76];
    __shared__ float hb[56], ha[56];
    __shared__ __align__(16) float w0s[56 * 12];
    __shared__ float b0bs[12], b0as[12];

    const int tid = threadIdx.x;
    const int img = blockIdx.x;

    const float* xim = x + img * 3072;
    for (int i = tid; i < 3072; i += 256) xs[i] = xim[i];
    for (int i = tid; i < 56 * 76; i += 256) {
        int oc = i / 76, t = i % 76;
        wh[i] = (t < 75) ? head_w[oc * 75 + t] : 0.f;
    }
    if (tid < 56) { hb[tid] = head_b[tid]; ha[tid] = head_a[tid]; }
    for (int i = tid; i < 672; i += 256) {
        int oc = i / 12, s = i % 12;
        w0s[i] = b0_w[s * 56 + oc];
    }
    if (tid < 12) { b0bs[tid] = b0_b[tid]; b0as[tid] = b0_a[tid]; }
    __syncthreads();

    float* out = g_h1 + img * 12288;

    for (int k = 0; k < 4; k++) {
        const int pix = k * 256 + tid;
        const int y = pix >> 5, x0 = pix & 31;

        float xr[76];
        xr[75] = 0.f;
#pragma unroll
        for (int ic = 0; ic < 3; ic++)
#pragma unroll
        for (int ky = 0; ky < 5; ky++) {
            const int yy = y + ky - 2;
#pragma unroll
            for (int kx = 0; kx < 5; kx++) {
                const int xx = x0 + kx - 2;
                const bool ok = (yy >= 0) & (yy < 32) & (xx >= 0) & (xx < 32);
                xr[ic * 25 + ky * 5 + kx] = ok ? xs[ic * 1024 + yy * 32 + xx] : 0.f;
            }
        }

        float acc[12];
#pragma unroll
        for (int s = 0; s < 12; s++) acc[s] = b0bs[s];

#pragma unroll 1
        for (int oc = 0; oc < 56; oc++) {
            float a = hb[oc];
            const float4* wp = (const float4*)(wh + oc * 76);
#pragma unroll
            for (int j = 0; j < 19; j++) {
                float4 w4 = wp[j];
                a = fmaf(xr[4 * j + 0], w4.x, a);
                a = fmaf(xr[4 * j + 1], w4.y, a);
                a = fmaf(xr[4 * j + 2], w4.z, a);
                a = fmaf(xr[4 * j + 3], w4.w, a);
            }
            const float h = (a >= 0.f) ? a : ha[oc] * a;
            const float4* q = (const float4*)(w0s + oc * 12);
            float4 q0 = q[0], q1 = q[1], q2 = q[2];
            acc[0]  = fmaf(h, q0.x, acc[0]);  acc[1]  = fmaf(h, q0.y, acc[1]);
            acc[2]  = fmaf(h, q0.z, acc[2]);  acc[3]  = fmaf(h, q0.w, acc[3]);
            acc[4]  = fmaf(h, q1.x, acc[4]);  acc[5]  = fmaf(h, q1.y, acc[5]);
            acc[6]  = fmaf(h, q1.z, acc[6]);  acc[7]  = fmaf(h, q1.w, acc[7]);
            acc[8]  = fmaf(h, q2.x, acc[8]);  acc[9]  = fmaf(h, q2.y, acc[9]);
            acc[10] = fmaf(h, q2.z, acc[10]); acc[11] = fmaf(h, q2.w, acc[11]);
        }

#pragma unroll
        for (int s = 0; s < 12; s++) {
            float v = acc[s];
            v = (v >= 0.f) ? v : b0as[s] * v;
            out[s * 1024 + pix] = v;
        }
    }
}

// ---------------------------------------------------------------------------
// Kernel 2: four 3x3 convs (12->12, pad1), PReLU(b5_a) after the last.
// Single smem buffer (results staged in registers) -> 77KB -> 2 CTAs/SM.
// ---------------------------------------------------------------------------
__global__ __launch_bounds__(256, 2) void k_body(
    const float* __restrict__ w1, const float* __restrict__ bb1,
    const float* __restrict__ w2, const float* __restrict__ bb2,
    const float* __restrict__ w3, const float* __restrict__ bb3,
    const float* __restrict__ w4, const float* __restrict__ bb4,
    const float* __restrict__ b5a)
{
    extern __shared__ float sm[];
    float* buf = sm;               // 12288
    float* ws  = sm + 12288;       // 4*1728 = 6912, [l][oc][ic][12pad]
    float* bs  = sm + 19200;       // 48
    float* a5  = sm + 19248;       // 12

    const int tid = threadIdx.x;
    const int img = blockIdx.x;

    const float* wl[4] = {w1, w2, w3, w4};
    const float* bl[4] = {bb1, bb2, bb3, bb4};
    for (int l = 0; l < 4; l++) {
        const float* w = wl[l];
        for (int i = tid; i < 1728; i += 256) {
            int pr = i / 12, t = i % 12;
            ws[l * 1728 + i] = (t < 9) ? w[pr * 9 + t] : 0.f;
        }
        if (tid < 12) bs[l * 12 + tid] = bl[l][tid];
    }
    if (tid < 12) a5[tid] = b5a[tid];

    const float* src_g = g_h1 + img * 12288;
    for (int i = tid; i < 12288; i += 256) buf[i] = src_g[i];
    __syncthreads();

    float* gout = g_h5 + img * 12288;

    for (int l = 0; l < 4; l++) {
        const float* w = ws + l * 1728;
        const float* bb = bs + l * 12;
        float res[4][12];

#pragma unroll
        for (int k = 0; k < 4; k++) {
            const int pix = k * 256 + tid;
            const int y = pix >> 5, x = pix & 31;
            float acc[12];
#pragma unroll
            for (int o = 0; o < 12; o++) acc[o] = bb[o];

            const bool yu = y > 0, yd = y < 31, xl = x > 0, xr = x < 31;
#pragma unroll 1
            for (int ic = 0; ic < 12; ic++) {
                const float* sp = buf + ic * 1024 + y * 32 + x;
                const float n0 = (yu && xl) ? sp[-33] : 0.f;
                const float n1 = yu ? sp[-32] : 0.f;
                const float n2 = (yu && xr) ? sp[-31] : 0.f;
                const float n3 = xl ? sp[-1] : 0.f;
                const float n4 = sp[0];
                const float n5 = xr ? sp[1] : 0.f;
                const float n6 = (yd && xl) ? sp[31] : 0.f;
                const float n7 = yd ? sp[32] : 0.f;
                const float n8 = (yd && xr) ? sp[33] : 0.f;
#pragma unroll
                for (int oc = 0; oc < 12; oc++) {
                    const float4* wp = (const float4*)(w + (oc * 12 + ic) * 12);
                    float4 a0 = wp[0], a1 = wp[1], a2 = wp[2];
                    float s0 = acc[oc];
                    s0 = fmaf(n0, a0.x, s0); s0 = fmaf(n1, a0.y, s0);
                    s0 = fmaf(n2, a0.z, s0); s0 = fmaf(n3, a0.w, s0);
                    s0 = fmaf(n4, a1.x, s0); s0 = fmaf(n5, a1.y, s0);
                    s0 = fmaf(n6, a1.z, s0); s0 = fmaf(n7, a1.w, s0);
                    s0 = fmaf(n8, a2.x, s0);
                    acc[oc] = s0;
                }
            }
#pragma unroll
            for (int o = 0; o < 12; o++) res[k][o] = acc[o];
        }

        if (l == 3) {
#pragma unroll
            for (int k = 0; k < 4; k++) {
                const int pix = k * 256 + tid;
#pragma unroll
                for (int oc = 0; oc < 12; oc++) {
                    float v = res[k][oc];
                    v = (v >= 0.f) ? v : a5[oc] * v;
                    gout[oc * 1024 + pix] = v;
                }
            }
        } else {
            __syncthreads();
#pragma unroll
            for (int k = 0; k < 4; k++) {
                const int pix = k * 256 + tid;
#pragma unroll
                for (int oc = 0; oc < 12; oc++)
                    buf[oc * 1024 + pix] = res[k][oc];
            }
            __syncthreads();
        }
    }
}

// ---------------------------------------------------------------------------
// Kernel 3 (fused): b6 1x1 (12->56) + PReLU computed in smem, then
// 9x9 stride-2 transposed conv (56->3), pad4, outpad1.
// Block = one image quadrant of output (64x64 out -> 32x32 per block).
// Channels processed in 2 chunks of 28 to keep smem ~103KB -> 2 CTAs/SM.
// 512 threads: 4 parity classes x 128 threads, 2 output px/thread.
// ---------------------------------------------------------------------------
__global__ __launch_bounds__(512) void k_tail(
    const float* __restrict__ b6_w, const float* __restrict__ b6_b,
    const float* __restrict__ b6_a,
    const float* __restrict__ tail_w, const float* __restrict__ tail_b,
    float* __restrict__ out)
{
    extern __shared__ float sm[];
    float* h5t = sm;             // 12*400 = 4800  [s][r*20+s20], zero-padded
    float* h6c = sm + 4800;      // 28*400 = 11200 chunk of expanded channels
    float* wtc = sm + 16000;     // 81*28*4 = 9072 [tap][cl][oc4]
    float* b6w = sm + 25072;     // 672 [c56][s12]
    float* b6b = sm + 25744;     // 56
    float* b6a = sm + 25800;     // 56
    float* tb  = sm + 25856;     // 4

    const int tid = threadIdx.x;
    const int bid = blockIdx.x;
    const int img = bid >> 2;
    const int tIdx = bid & 3;
    const int OY0 = (tIdx >> 1) * 32, OX0 = (tIdx & 1) * 32;
    const int IY0 = OY0 / 2 - 2, IX0 = OX0 / 2 - 2;

    // --- stage h5 tile (zero-padded 20x20 halo region) + b6 params ---
    const float* h5g = g_h5 + img * 12288;
    for (int i = tid; i < 4800; i += 512) {
        const int c = i / 400;
        const int p = i % 400;
        const int r = p / 20, s = p % 20;
        const int iy = IY0 + r, ix = IX0 + s;
        float v = 0.f;
        if (iy >= 0 && iy < 32 && ix >= 0 && ix < 32)
            v = h5g[c * 1024 + iy * 32 + ix];
        h5t[i] = v;
    }
    for (int i = tid; i < 672; i += 512) b6w[i] = b6_w[i];
    if (tid < 56) { b6b[tid] = b6_b[tid]; b6a[tid] = b6_a[tid]; }
    if (tid < 3) tb[tid] = tail_b[tid];
    __syncthreads();

    // parity class / pixel mapping
    const int phase = tid >> 7;            // 0..3
    const int ry = phase & 1, rx = phase >> 1;
    const int t = tid & 127;
    const int sx = t & 15, sy = t >> 4;    // sy in 0..7; pixels rows sy, sy+8
    const int nky = 5 - ry, nkx = 5 - rx;

    float acc[2][3];
#pragma unroll
    for (int p = 0; p < 2; p++)
#pragma unroll
        for (int o = 0; o < 3; o++) acc[p][o] = tb[o];

    for (int cc = 0; cc < 2; cc++) {
        const int cbase = cc * 28;

        // --- phase A: expand 12->28 chunk channels (1x1 conv + PReLU) ---
        for (int i = tid; i < 11200; i += 512) {
            const int cl = i / 400;
            const int p400 = i % 400;
            const int r = p400 / 20, s = p400 % 20;
            const int iy = IY0 + r, ix = IX0 + s;
            const bool valid = (iy >= 0) & (iy < 32) & (ix >= 0) & (ix < 32);
            const int c = cbase + cl;
            const float4* wq = (const float4*)(b6w + c * 12);
            const float4 q0 = wq[0], q1 = wq[1], q2 = wq[2];
            float a = b6b[c];
            a = fmaf(h5t[p400],          q0.x, a);
            a = fmaf(h5t[400 + p400],    q0.y, a);
            a = fmaf(h5t[800 + p400],    q0.z, a);
            a = fmaf(h5t[1200 + p400],   q0.w, a);
            a = fmaf(h5t[1600 + p400],   q1.x, a);
            a = fmaf(h5t[2000 + p400],   q1.y, a);
            a = fmaf(h5t[2400 + p400],   q1.z, a);
            a = fmaf(h5t[2800 + p400],   q1.w, a);
            a = fmaf(h5t[3200 + p400],   q2.x, a);
            a = fmaf(h5t[3600 + p400],   q2.y, a);
            a = fmaf(h5t[4000 + p400],   q2.z, a);
            a = fmaf(h5t[4400 + p400],   q2.w, a);
            a = (a >= 0.f) ? a : b6a[c] * a;
            h6c[i] = valid ? a : 0.f;
        }
        // load tail-weight chunk [tap81][cl28][oc4pad]
        for (int i = tid; i < 9072; i += 512) {
            const int oc = i & 3;
            const int rest = i >> 2;
            const int cl = rest % 28;
            const int tp = rest / 28;
            wtc[i] = (oc < 3) ? tail_w[(cbase + cl) * 243 + oc * 81 + tp] : 0.f;
        }
        __syncthreads();

        // --- phase B: transposed conv over this channel chunk ---
#pragma unroll 1
        for (int a = 0; a < nky; a++) {
            const int ky = (ry == 0) ? (8 - 2 * a) : (7 - 2 * a);
            const int dr = (ry == 0) ? a : (a + 1);
#pragma unroll 1
            for (int b = 0; b < nkx; b++) {
                const int kx = (rx == 0) ? (8 - 2 * b) : (7 - 2 * b);
                const int dc = (rx == 0) ? b : (b + 1);
                const float* wp = wtc + (ky * 9 + kx) * 28 * 4;
                const float* hp = h6c + (sy + dr) * 20 + (sx + dc);
#pragma unroll 4
                for (int cl = 0; cl < 28; cl++) {
                    const float4 w4 = *(const float4*)(wp + cl * 4);  // broadcast
                    const float h0 = hp[cl * 400];
                    const float h1 = hp[cl * 400 + 160];
                    acc[0][0] = fmaf(h0, w4.x, acc[0][0]);
                    acc[0][1] = fmaf(h0, w4.y, acc[0][1]);
                    acc[0][2] = fmaf(h0, w4.z, acc[0][2]);
                    acc[1][0] = fmaf(h1, w4.x, acc[1][0]);
                    acc[1][1] = fmaf(h1, w4.y, acc[1][1]);
                    acc[1][2] = fmaf(h1, w4.z, acc[1][2]);
                }
            }
        }
        __syncthreads();
    }

    float* o = out + img * 3 * 4096;
#pragma unroll
    for (int p = 0; p < 2; p++) {
        const int oy = OY0 + 2 * (sy + 8 * p) + ry;
        const int ox = OX0 + 2 * sx + rx;
#pragma unroll
        for (int oc = 0; oc < 3; oc++)
            o[oc * 4096 + oy * 64 + ox] = acc[p][oc];
    }
}

// ---------------------------------------------------------------------------
extern "C" void kernel_launch(void* const* d_in, const int* in_sizes, int n_in,
                              void* d_out, int out_size)
{
    const float* x      = (const float*)d_in[0];
    const float* head_w = (const float*)d_in[1];
    const float* head_b = (const float*)d_in[2];
    const float* head_a = (const float*)d_in[3];
    const float* b0_w   = (const float*)d_in[4];
    const float* b0_b   = (const float*)d_in[5];
    const float* b0_a   = (const float*)d_in[6];
    const float* b1_w   = (const float*)d_in[7];
    const float* b1_b   = (const float*)d_in[8];
    const float* b2_w   = (const float*)d_in[9];
    const float* b2_b   = (const float*)d_in[10];
    const float* b3_w   = (const float*)d_in[11];
    const float* b3_b   = (const float*)d_in[12];
    const float* b4_w   = (const float*)d_in[13];
    const float* b4_b   = (const float*)d_in[14];
    const float* b5_a   = (const float*)d_in[15];
    const float* b6_w   = (const float*)d_in[16];
    const float* b6_b   = (const float*)d_in[17];
    const float* b6_a   = (const float*)d_in[18];
    const float* tail_w = (const float*)d_in[19];
    const float* tail_b = (const float*)d_in[20];

    const int SM2 = 19260 * 4;   // k_body dynamic smem (77 KB)
    const int SM4 = 25860 * 4;   // k_tail dynamic smem (103.4 KB)
    cudaFuncSetAttribute(k_body, cudaFuncAttributeMaxDynamicSharedMemorySize, SM2);
    cudaFuncSetAttribute(k_tail, cudaFuncAttributeMaxDynamicSharedMemorySize, SM4);

    k_head<<<1024, 256>>>(x, head_w, head_b, head_a, b0_w, b0_b, b0_a);
    k_body<<<1024, 256, SM2>>>(b1_w, b1_b, b2_w, b2_b, b3_w, b3_b, b4_w, b4_b, b5_a);
    k_tail<<<4096, 512, SM4>>>(b6_w, b6_b, b6_a, tail_w, tail_b, (float*)d_out);
}

// round 3
// speedup vs baseline: 1.9737x; 1.4967x over previous
#include <cuda_runtime.h>
#include <cuda_bf16.h>

// FSRCNN: BS=1024, D=56, S=12, H=W=32 -> out 3x64x64
__device__ float g_h1[1024 * 12 * 1024];   // after b0 + prelu
__device__ float g_h5[1024 * 12 * 1024];   // after b4 + prelu(b5_a)

// ---------------------------------------------------------------------------
// Kernel 1: head 5x5 conv (3->56, pad2) + PReLU + b0 1x1 (56->12) + PReLU
// ---------------------------------------------------------------------------
__global__ __launch_bounds__(256) void k_head(
    const float* __restrict__ x,
    const float* __restrict__ head_w, const float* __restrict__ head_b,
    const float* __restrict__ head_a,
    const float* __restrict__ b0_w, const float* __restrict__ b0_b,
    const float* __restrict__ b0_a)
{
    __shared__ float xs[3 * 1024];
    __shared__ __align__(16) float wh[56 * 76];
    __shared__ float hb[56], ha[56];
    __shared__ __align__(16) float w0s[56 * 12];
    __shared__ float b0bs[12], b0as[12];

    const int tid = threadIdx.x;
    const int img = blockIdx.x;

    const float* xim = x + img * 3072;
    for (int i = tid; i < 3072; i += 256) xs[i] = xim[i];
    for (int i = tid; i < 56 * 76; i += 256) {
        int oc = i / 76, t = i % 76;
        wh[i] = (t < 75) ? head_w[oc * 75 + t] : 0.f;
    }
    if (tid < 56) { hb[tid] = head_b[tid]; ha[tid] = head_a[tid]; }
    for (int i = tid; i < 672; i += 256) {
        int oc = i / 12, s = i % 12;
        w0s[i] = b0_w[s * 56 + oc];
    }
    if (tid < 12) { b0bs[tid] = b0_b[tid]; b0as[tid] = b0_a[tid]; }
    __syncthreads();

    float* out = g_h1 + img * 12288;

    for (int k = 0; k < 4; k++) {
        const int pix = k * 256 + tid;
        const int y = pix >> 5, x0 = pix & 31;

        float xr[76];
        xr[75] = 0.f;
#pragma unroll
        for (int ic = 0; ic < 3; ic++)
#pragma unroll
        for (int ky = 0; ky < 5; ky++) {
            const int yy = y + ky - 2;
#pragma unroll
            for (int kx = 0; kx < 5; kx++) {
                const int xx = x0 + kx - 2;
                const bool ok = (yy >= 0) & (yy < 32) & (xx >= 0) & (xx < 32);
                xr[ic * 25 + ky * 5 + kx] = ok ? xs[ic * 1024 + yy * 32 + xx] : 0.f;
            }
        }

        float acc[12];
#pragma unroll
        for (int s = 0; s < 12; s++) acc[s] = b0bs[s];

#pragma unroll 1
        for (int oc = 0; oc < 56; oc++) {
            float a = hb[oc];
            const float4* wp = (const float4*)(wh + oc * 76);
#pragma unroll
            for (int j = 0; j < 19; j++) {
                float4 w4 = wp[j];
                a = fmaf(xr[4 * j + 0], w4.x, a);
                a = fmaf(xr[4 * j + 1], w4.y, a);
                a = fmaf(xr[4 * j + 2], w4.z, a);
                a = fmaf(xr[4 * j + 3], w4.w, a);
            }
            const float h = (a >= 0.f) ? a : ha[oc] * a;
            const float4* q = (const float4*)(w0s + oc * 12);
            float4 q0 = q[0], q1 = q[1], q2 = q[2];
            acc[0]  = fmaf(h, q0.x, acc[0]);  acc[1]  = fmaf(h, q0.y, acc[1]);
            acc[2]  = fmaf(h, q0.z, acc[2]);  acc[3]  = fmaf(h, q0.w, acc[3]);
            acc[4]  = fmaf(h, q1.x, acc[4]);  acc[5]  = fmaf(h, q1.y, acc[5]);
            acc[6]  = fmaf(h, q1.z, acc[6]);  acc[7]  = fmaf(h, q1.w, acc[7]);
            acc[8]  = fmaf(h, q2.x, acc[8]);  acc[9]  = fmaf(h, q2.y, acc[9]);
            acc[10] = fmaf(h, q2.z, acc[10]); acc[11] = fmaf(h, q2.w, acc[11]);
        }

#pragma unroll
        for (int s = 0; s < 12; s++) {
            float v = acc[s];
            v = (v >= 0.f) ? v : b0as[s] * v;
            out[s * 1024 + pix] = v;
        }
    }
}

// ---------------------------------------------------------------------------
// Kernel 2: four 3x3 convs (12->12, pad1), PReLU(b5_a) after the last.
// Padded 34x34 smem image -> no bounds checks. Per-thread 4 pixels held in
// registers through the ic loop so weight LDS amortizes 4x.
// ---------------------------------------------------------------------------
__global__ __launch_bounds__(256, 2) void k_body(
    const float* __restrict__ w1, const float* __restrict__ bb1,
    const float* __restrict__ w2, const float* __restrict__ bb2,
    const float* __restrict__ w3, const float* __restrict__ bb3,
    const float* __restrict__ w4, const float* __restrict__ bb4,
    const float* __restrict__ b5a)
{
    extern __shared__ float sm[];
    float* buf = sm;               // 12*1156 = 13872 (34x34 padded)
    float* ws  = sm + 13872;       // 4*1728 = 6912, [l][oc*12+ic][12pad]
    float* bs  = sm + 20784;       // 48
    float* a5  = sm + 20832;       // 12

    const int tid = threadIdx.x;
    const int img = blockIdx.x;

    const float* wl[4] = {w1, w2, w3, w4};
    const float* bl[4] = {bb1, bb2, bb3, bb4};
    for (int l = 0; l < 4; l++) {
        const float* w = wl[l];
        for (int i = tid; i < 1728; i += 256) {
            int pr = i / 12, t = i % 12;
            ws[l * 1728 + i] = (t < 9) ? w[pr * 9 + t] : 0.f;
        }
        if (tid < 12) bs[l * 12 + tid] = bl[l][tid];
    }
    if (tid < 12) a5[tid] = b5a[tid];

    for (int i = tid; i < 13872; i += 256) buf[i] = 0.f;
    __syncthreads();

    const float* src_g = g_h1 + img * 12288;
    for (int i = tid; i < 12288; i += 256) {
        const int c = i >> 10, p = i & 1023;
        const int y = p >> 5, xx = p & 31;
        buf[c * 1156 + (y + 1) * 34 + (xx + 1)] = src_g[i];
    }
    __syncthreads();

    const int x = tid & 31;
    const int y0 = tid >> 5;
    int base[4];
#pragma unroll
    for (int k = 0; k < 4; k++) base[k] = (y0 + 8 * k + 1) * 34 + (x + 1);

    float* gout = g_h5 + img * 12288;

#pragma unroll 1
    for (int l = 0; l < 4; l++) {
        const float* w = ws + l * 1728;
        const float* bb = bs + l * 12;

        float acc[4][12];
#pragma unroll
        for (int k = 0; k < 4; k++)
#pragma unroll
            for (int o = 0; o < 12; o++) acc[k][o] = bb[o];

#pragma unroll 1
        for (int ic = 0; ic < 12; ic++) {
            const float* cb = buf + ic * 1156;
            float n[4][9];
#pragma unroll
            for (int k = 0; k < 4; k++) {
                const float* sp = cb + base[k];
                n[k][0] = sp[-35]; n[k][1] = sp[-34]; n[k][2] = sp[-33];
                n[k][3] = sp[-1];  n[k][4] = sp[0];   n[k][5] = sp[1];
                n[k][6] = sp[33];  n[k][7] = sp[34];  n[k][8] = sp[35];
            }
#pragma unroll
            for (int oc = 0; oc < 12; oc++) {
                const float4* wp = (const float4*)(w + (oc * 12 + ic) * 12);
                const float4 a0 = wp[0], a1 = wp[1], a2 = wp[2];
#pragma unroll
                for (int k = 0; k < 4; k++) {
                    float s0 = acc[k][oc];
                    s0 = fmaf(n[k][0], a0.x, s0); s0 = fmaf(n[k][1], a0.y, s0);
                    s0 = fmaf(n[k][2], a0.z, s0); s0 = fmaf(n[k][3], a0.w, s0);
                    s0 = fmaf(n[k][4], a1.x, s0); s0 = fmaf(n[k][5], a1.y, s0);
                    s0 = fmaf(n[k][6], a1.z, s0); s0 = fmaf(n[k][7], a1.w, s0);
                    s0 = fmaf(n[k][8], a2.x, s0);
                    acc[k][oc] = s0;
                }
            }
        }

        if (l == 3) {
#pragma unroll
            for (int k = 0; k < 4; k++) {
                const int pix = k * 256 + tid;
#pragma unroll
                for (int oc = 0; oc < 12; oc++) {
                    float v = acc[k][oc];
                    v = (v >= 0.f) ? v : a5[oc] * v;
                    gout[oc * 1024 + pix] = v;
                }
            }
        } else {
            __syncthreads();
#pragma unroll
            for (int k = 0; k < 4; k++)
#pragma unroll
                for (int oc = 0; oc < 12; oc++)
                    buf[oc * 1156 + base[k]] = acc[k][oc];
            __syncthreads();
        }
    }
}

// ---------------------------------------------------------------------------
// Kernel 3 (fused): b6 1x1 (12->56) + PReLU in smem, then 9x9 stride-2
// transposed conv (56->3), pad4, outpad1. Block = one output quadrant (32x32).
// Each thread owns one SITE = 4 output pixels (all parities) -> balanced.
// h6 stored [pixel][channel] -> float4 LDS; weights [tap][oc][cl] broadcast.
// Channels in 2 chunks of 28; smem 94.4KB -> 2 CTAs/SM.
// ---------------------------------------------------------------------------
__device__ __forceinline__ void tap_acc(const float4 h4, const float* wt, int g, float* a)
{
    const float4 w0 = *(const float4*)(wt + g);
    const float4 w1 = *(const float4*)(wt + 28 + g);
    const float4 w2 = *(const float4*)(wt + 56 + g);
    a[0] = fmaf(h4.x, w0.x, a[0]); a[0] = fmaf(h4.y, w0.y, a[0]);
    a[0] = fmaf(h4.z, w0.z, a[0]); a[0] = fmaf(h4.w, w0.w, a[0]);
    a[1] = fmaf(h4.x, w1.x, a[1]); a[1] = fmaf(h4.y, w1.y, a[1]);
    a[1] = fmaf(h4.z, w1.z, a[1]); a[1] = fmaf(h4.w, w1.w, a[1]);
    a[2] = fmaf(h4.x, w2.x, a[2]); a[2] = fmaf(h4.y, w2.y, a[2]);
    a[2] = fmaf(h4.z, w2.z, a[2]); a[2] = fmaf(h4.w, w2.w, a[2]);
}

__device__ __forceinline__ void acc1(const float* hp, const float* wa, float* A)
{
#pragma unroll
    for (int g = 0; g < 28; g += 4) {
        const float4 h4 = *(const float4*)(hp + g);
        tap_acc(h4, wa, g, A);
    }
}
__device__ __forceinline__ void acc2(const float* hp, const float* wa, float* A,
                                     const float* wb, float* B)
{
#pragma unroll
    for (int g = 0; g < 28; g += 4) {
        const float4 h4 = *(const float4*)(hp + g);
        tap_acc(h4, wa, g, A);
        tap_acc(h4, wb, g, B);
    }
}
__device__ __forceinline__ void acc4(const float* hp,
                                     const float* w00, float* A0,
                                     const float* w01, float* A1,
                                     const float* w10, float* A2,
                                     const float* w11, float* A3)
{
#pragma unroll
    for (int g = 0; g < 28; g += 4) {
        const float4 h4 = *(const float4*)(hp + g);
        tap_acc(h4, w00, g, A0);
        tap_acc(h4, w01, g, A1);
        tap_acc(h4, w10, g, A2);
        tap_acc(h4, w11, g, A3);
    }
}

__global__ __launch_bounds__(256, 2) void k_tail(
    const float* __restrict__ b6_w, const float* __restrict__ b6_b,
    const float* __restrict__ b6_a,
    const float* __restrict__ tail_w, const float* __restrict__ tail_b,
    float* __restrict__ out)
{
    extern __shared__ float sm[];
    float* h5t = sm;            // 12*400 = 4800   [s][p400]
    float* h6c = sm + 4800;     // 400*28 = 11200  [p400][cl28]
    float* wtc = sm + 16000;    // 81*3*28 = 6804  [tap][oc][cl]
    float* b6w = sm + 22804;    // 672
    float* b6b = sm + 23476;    // 56
    float* b6a = sm + 23532;    // 56
    float* tb  = sm + 23588;    // 4
    // total 23592 floats = 94368 B

    const int tid = threadIdx.x;
    const int bid = blockIdx.x;
    const int img = bid >> 2;
    const int tIdx = bid & 3;
    const int OY0 = (tIdx >> 1) * 32, OX0 = (tIdx & 1) * 32;
    const int IY0 = OY0 / 2 - 2, IX0 = OX0 / 2 - 2;

    // stage h5 tile (zero-padded 20x20 halo) + params
    const float* h5g = g_h5 + img * 12288;
    for (int i = tid; i < 4800; i += 256) {
        const int c = i / 400;
        const int p = i % 400;
        const int r = p / 20, s = p % 20;
        const int iy = IY0 + r, ix = IX0 + s;
        float v = 0.f;
        if (iy >= 0 && iy < 32 && ix >= 0 && ix < 32)
            v = h5g[c * 1024 + iy * 32 + ix];
        h5t[i] = v;
    }
    for (int i = tid; i < 672; i += 256) b6w[i] = b6_w[i];
    if (tid < 56) { b6b[tid] = b6_b[tid]; b6a[tid] = b6_a[tid]; }
    if (tid < 3) tb[tid] = tail_b[tid];
    __syncthreads();

    // site mapping
    const int sy = tid >> 4, sx = tid & 15;

    // per-thread expand positions p0, p1 (cover all 400 tile pixels)
    const int p0 = tid, p1 = tid + 256;
    const int r0 = p0 / 20, c0 = p0 % 20;
    const int r1 = p1 / 20, c1 = p1 % 20;
    const bool have1 = (p1 < 400);
    const bool val0 = (IY0 + r0 >= 0) && (IY0 + r0 < 32) && (IX0 + c0 >= 0) && (IX0 + c0 < 32);
    const bool val1 = have1 && (IY0 + r1 >= 0) && (IY0 + r1 < 32) && (IX0 + c1 >= 0) && (IX0 + c1 < 32);

    float v0[12], v1[12];
#pragma unroll
    for (int s = 0; s < 12; s++) {
        v0[s] = h5t[s * 400 + p0];
        v1[s] = have1 ? h5t[s * 400 + p1] : 0.f;
    }

    float acc[4][3];
#pragma unroll
    for (int p = 0; p < 4; p++)
#pragma unroll
        for (int o = 0; o < 3; o++) acc[p][o] = tb[o];

#pragma unroll 1
    for (int cc = 0; cc < 2; cc++) {
        const int cb56 = cc * 28;
        if (cc) __syncthreads();    // protect wtc/h6c from previous readers

        // stage tail-weight chunk [tap81][oc3][cl28]
        for (int i = tid; i < 6804; i += 256) {
            const int tap = i / 84;
            const int rest = i % 84;
            const int oc = rest / 28;
            const int cl = rest % 28;
            wtc[i] = tail_w[(cb56 + cl) * 243 + oc * 81 + tap];
        }

        // phase A: expand 12 -> 28 channels, write [p][cl]
#pragma unroll 1
        for (int cl = 0; cl < 28; cl++) {
            const int c = cb56 + cl;
            const float4* wq = (const float4*)(b6w + c * 12);
            const float4 q0 = wq[0], q1 = wq[1], q2 = wq[2];
            const float bb = b6b[c], aa = b6a[c];

            float a = bb;
            a = fmaf(v0[0], q0.x, a);  a = fmaf(v0[1], q0.y, a);
            a = fmaf(v0[2], q0.z, a);  a = fmaf(v0[3], q0.w, a);
            a = fmaf(v0[4], q1.x, a);  a = fmaf(v0[5], q1.y, a);
            a = fmaf(v0[6], q1.z, a);  a = fmaf(v0[7], q1.w, a);
            a = fmaf(v0[8], q2.x, a);  a = fmaf(v0[9], q2.y, a);
            a = fmaf(v0[10], q2.z, a); a = fmaf(v0[11], q2.w, a);
            a = (a >= 0.f) ? a : aa * a;
            h6c[p0 * 28 + cl] = val0 ? a : 0.f;

            if (have1) {
                float b = bb;
                b = fmaf(v1[0], q0.x, b);  b = fmaf(v1[1], q0.y, b);
                b = fmaf(v1[2], q0.z, b);  b = fmaf(v1[3], q0.w, b);
                b = fmaf(v1[4], q1.x, b);  b = fmaf(v1[5], q1.y, b);
                b = fmaf(v1[6], q1.z, b);  b = fmaf(v1[7], q1.w, b);
                b = fmaf(v1[8], q2.x, b);  b = fmaf(v1[9], q2.y, b);
                b = fmaf(v1[10], q2.z, b); b = fmaf(v1[11], q2.w, b);
                b = (b >= 0.f) ? b : aa * b;
                h6c[p1 * 28 + cl] = val1 ? b : 0.f;
            }
        }
        __syncthreads();

        // phase B: transposed conv, all 4 parities per thread-site
        // dr=0 row (ky1 invalid)
        {
            const float* hr = h6c + (sy * 20 + sx) * 28;
            // dc = 0
            acc1(hr, wtc + (8 * 9 + 8) * 84, acc[0]);
            // dc = 1..4
#pragma unroll 1
            for (int dc = 1; dc < 5; dc++) {
                const int kx0 = 8 - 2 * dc, kx1 = 9 - 2 * dc;
                acc2(hr + dc * 28,
                     wtc + (8 * 9 + kx0) * 84, acc[0],
                     wtc + (8 * 9 + kx1) * 84, acc[1]);
            }
        }
#pragma unroll 1
        for (int dr = 1; dr < 5; dr++) {
            const int ky0 = 8 - 2 * dr, ky1 = 9 - 2 * dr;
            const float* hr = h6c + ((sy + dr) * 20 + sx) * 28;
            // dc = 0
            acc2(hr,
                 wtc + (ky0 * 9 + 8) * 84, acc[0],
                 wtc + (ky1 * 9 + 8) * 84, acc[2]);
#pragma unroll 1
            for (int dc = 1; dc < 5; dc++) {
                const int kx0 = 8 - 2 * dc, kx1 = 9 - 2 * dc;
                acc4(hr + dc * 28,
                     wtc + (ky0 * 9 + kx0) * 84, acc[0],
                     wtc + (ky0 * 9 + kx1) * 84, acc[1],
                     wtc + (ky1 * 9 + kx0) * 84, acc[2],
                     wtc + (ky1 * 9 + kx1) * 84, acc[3]);
            }
        }
    }

    float* o = out + img * 3 * 4096;
#pragma unroll
    for (int par = 0; par < 4; par++) {
        const int ry = par >> 1, rx = par & 1;
        const int oy = OY0 + 2 * sy + ry;
        const int ox = OX0 + 2 * sx + rx;
#pragma unroll
        for (int oc = 0; oc < 3; oc++)
            o[oc * 4096 + oy * 64 + ox] = acc[par][oc];
    }
}

// ---------------------------------------------------------------------------
extern "C" void kernel_launch(void* const* d_in, const int* in_sizes, int n_in,
                              void* d_out, int out_size)
{
    const float* x      = (const float*)d_in[0];
    const float* head_w = (const float*)d_in[1];
    const float* head_b = (const float*)d_in[2];
    const float* head_a = (const float*)d_in[3];
    const float* b0_w   = (const float*)d_in[4];
    const float* b0_b   = (const float*)d_in[5];
    const float* b0_a   = (const float*)d_in[6];
    const float* b1_w   = (const float*)d_in[7];
    const float* b1_b   = (const float*)d_in[8];
    const float* b2_w   = (const float*)d_in[9];
    const float* b2_b   = (const float*)d_in[10];
    const float* b3_w   = (const float*)d_in[11];
    const float* b3_b   = (const float*)d_in[12];
    const float* b4_w   = (const float*)d_in[13];
    const float* b4_b   = (const float*)d_in[14];
    const float* b5_a   = (const float*)d_in[15];
    const float* b6_w   = (const float*)d_in[16];
    const float* b6_b   = (const float*)d_in[17];
    const float* b6_a   = (const float*)d_in[18];
    const float* tail_w = (const float*)d_in[19];
    const float* tail_b = (const float*)d_in[20];

    const int SM2 = 20844 * 4;   // k_body dynamic smem (83.4 KB)
    const int SM4 = 23592 * 4;   // k_tail dynamic smem (94.4 KB)
    cudaFuncSetAttribute(k_body, cudaFuncAttributeMaxDynamicSharedMemorySize, SM2);
    cudaFuncSetAttribute(k_tail, cudaFuncAttributeMaxDynamicSharedMemorySize, SM4);

    k_head<<<1024, 256>>>(x, head_w, head_b, head_a, b0_w, b0_b, b0_a);
    k_body<<<1024, 256, SM2>>>(b1_w, b1_b, b2_w, b2_b, b3_w, b3_b, b4_w, b4_b, b5_a);
    k_tail<<<4096, 256, SM4>>>(b6_w, b6_b, b6_a, tail_w, tail_b, (float*)d_out);
}